// round 14
// baseline (speedup 1.0000x reference)
#include <cuda_runtime.h>
#include <cuda_fp16.h>
#include <cstdint>

// ============================================================================
// out[4096,4096] = x @ W^T + b  (fp32).
// Single-pass fp16 warp-MMA GEMM (mma.sync m16n8k16.f32.f16.f16.f32).
// CTA tile 128x128, split-K=2 (32 k-tiles of 64 per CTA), 4 warps @ 64x64,
// 3-stage cp.async ring, 2 CTAs/SM. Output via red.global.add.f32
// (deterministic: exactly 2 commutative fp32 addends per element).
// ============================================================================

#define DIM 4096
#define BM 128
#define BN 128
#define BK 64
#define NKT_H 32                // k-tiles per CTA (half of 64)
#define THREADS 128
#define STAGES 3

// per-stage smem: A 16K | B 16K = 32KB (128B rows, 8x16B chunks, XOR swizzle)
#define STAGE_BYTES 32768
#define OFF_A 0
#define OFF_B 16384
#define SM_BIAS 0               // 128 floats
#define SM_TILES 1024
#define SMEM_TOTAL (SM_TILES + STAGES * STAGE_BYTES)   // 99328 (x2 CTAs = 194KB/SM)

// ---------------------------------------------------------------------------
// Scratch: fp16 copies of x and W
// ---------------------------------------------------------------------------
__device__ __align__(256) __half g_x[(size_t)DIM * DIM];
__device__ __align__(256) __half g_w[(size_t)DIM * DIM];

// ---------------------------------------------------------------------------
// Helpers
// ---------------------------------------------------------------------------
static __device__ __forceinline__ uint32_t smem_u32(const void* p) {
    uint32_t a;
    asm("{ .reg .u64 t; cvta.to.shared.u64 t, %1; cvt.u32.u64 %0, t; }"
        : "=r"(a) : "l"(p));
    return a;
}

static __device__ __forceinline__ void cp16(uint32_t s, const void* g) {
    asm volatile("cp.async.cg.shared.global [%0], [%1], 16;" :: "r"(s), "l"(g));
}

static __device__ __forceinline__ void ldsm4(uint32_t* r, uint32_t a) {
    asm volatile("ldmatrix.sync.aligned.m8n8.x4.shared.b16 {%0,%1,%2,%3}, [%4];"
                 : "=r"(r[0]), "=r"(r[1]), "=r"(r[2]), "=r"(r[3]) : "r"(a));
}

static __device__ __forceinline__ void mma16816(float* c, const uint32_t* a,
                                                const uint32_t* b) {
    asm volatile(
        "mma.sync.aligned.m16n8k16.row.col.f32.f16.f16.f32 "
        "{%0,%1,%2,%3}, {%4,%5,%6,%7}, {%8,%9}, {%0,%1,%2,%3};"
        : "+f"(c[0]), "+f"(c[1]), "+f"(c[2]), "+f"(c[3])
        : "r"(a[0]), "r"(a[1]), "r"(a[2]), "r"(a[3]), "r"(b[0]), "r"(b[1]));
}

static __device__ __forceinline__ void redadd(float* p, float v) {
    asm volatile("red.global.add.f32 [%0], %1;" :: "l"(p), "f"(v) : "memory");
}

// ---------------------------------------------------------------------------
// Convert + zero kernel: seg 0 -> x fp16, seg 1 -> W fp16, seg 2 -> zero out.
// ---------------------------------------------------------------------------
__global__ __launch_bounds__(256) void convert_kernel(const float* __restrict__ x,
                                                      const float* __restrict__ W,
                                                      float* __restrict__ out) {
    const int seg_blocks = (int)(gridDim.x / 3);
    const int seg = (int)blockIdx.x / seg_blocks;
    const int blk = (int)blockIdx.x - seg * seg_blocks;
    size_t i = ((size_t)blk * blockDim.x + threadIdx.x) * 8;

    if (seg == 2) {
        float4 z = make_float4(0.f, 0.f, 0.f, 0.f);
        *reinterpret_cast<float4*>(out + i) = z;
        *reinterpret_cast<float4*>(out + i + 4) = z;
        return;
    }
    const float* src = seg ? W : x;
    __half* dst = seg ? g_w : g_x;
    float4 v0 = *reinterpret_cast<const float4*>(src + i);
    float4 v1 = *reinterpret_cast<const float4*>(src + i + 4);
    __half2 h[4];
    h[0] = __floats2half2_rn(v0.x, v0.y);
    h[1] = __floats2half2_rn(v0.z, v0.w);
    h[2] = __floats2half2_rn(v1.x, v1.y);
    h[3] = __floats2half2_rn(v1.z, v1.w);
    *reinterpret_cast<uint4*>(dst + i) = *reinterpret_cast<const uint4*>(h);
}

// ---------------------------------------------------------------------------
// Stage loader (128 threads): rows 128B wide (64 halfs); chunk cc of row r at
//   r*128 + ((cc ^ (r&7))<<4)  -> conflict-free for cp.async AND ldmatrix.
// ---------------------------------------------------------------------------
static __device__ __forceinline__ void load_stage(uint32_t sb, int stage, int kt,
                                                  int tm, int tn, int tid) {
    uint32_t st = sb + SM_TILES + stage * STAGE_BYTES;
    const uint32_t k0 = (uint32_t)kt * BK;
#pragma unroll
    for (int i = 0; i < 8; ++i) {          // A: 1024 chunks / 128 thr
        int c = i * 128 + tid;
        int r = c >> 3, cc = c & 7;
        uint32_t so = (uint32_t)r * 128 + (uint32_t)((cc ^ (r & 7)) << 4);
        cp16(st + OFF_A + so, g_x + (size_t)(tm * BM + r) * DIM + k0 + cc * 8);
    }
#pragma unroll
    for (int i = 0; i < 8; ++i) {          // B: 1024 chunks / 128 thr
        int c = i * 128 + tid;
        int r = c >> 3, cc = c & 7;
        uint32_t so = (uint32_t)r * 128 + (uint32_t)((cc ^ (r & 7)) << 4);
        cp16(st + OFF_B + so, g_w + (size_t)(tn * BN + r) * DIM + k0 + cc * 8);
    }
}

// ---------------------------------------------------------------------------
// GEMM: D(128x128) partial over K-half, red.add into out (+ bias from kh=0).
// 4 warps @ 64x64: wm = wid&1 (2 x 64 rows), wn = wid>>1 (2 x 64 cols).
// ---------------------------------------------------------------------------
__global__ __launch_bounds__(THREADS, 2) void gemm_kernel(const float* __restrict__ bias,
                                                          float* __restrict__ out) {
    extern __shared__ __align__(1024) char smem[];
    uint32_t sb = smem_u32(smem);
    const int tid = threadIdx.x;
    const int lane = tid & 31, wid = tid >> 5;
    const int wm = wid & 1, wn = wid >> 1;

    // grid = 2048: low 10 bits -> tile (tm fast), bit 10 -> K half
    const int pid = blockIdx.x;
    const int tile = pid & 1023;
    const int kh = pid >> 10;
    const int tm = tile & 31;              // 0..31
    const int tn = tile >> 5;              // 0..31
    const int kbase = kh * NKT_H;

    reinterpret_cast<float*>(smem + SM_BIAS)[tid] = bias[tn * BN + tid];

    // per-lane ldmatrix address components (row*128 base + row-swizzle key r&7)
    uint32_t aoff[4], asw[4];
#pragma unroll
    for (int mt = 0; mt < 4; ++mt) {
        int r = wm * 64 + mt * 16 + (lane & 15);
        aoff[mt] = (uint32_t)r * 128;
        asw[mt] = (uint32_t)(r & 7);
    }
    uint32_t boff[4], bsw[4];
#pragma unroll
    for (int jj = 0; jj < 4; ++jj) {
        int r = wn * 64 + jj * 16 + ((lane >> 4) & 1) * 8 + (lane & 7);
        boff[jj] = (uint32_t)r * 128;
        bsw[jj] = (uint32_t)(r & 7);
    }
    const uint32_t cAsel = (uint32_t)(lane >> 4);        // A k-chunk select (0/1)
    const uint32_t cBsel = (uint32_t)((lane >> 3) & 1);  // B k-chunk select (0/1)

    float acc[4][8][4];
#pragma unroll
    for (int mt = 0; mt < 4; ++mt)
#pragma unroll
        for (int nt = 0; nt < 8; ++nt)
#pragma unroll
            for (int k = 0; k < 4; ++k) acc[mt][nt][k] = 0.f;

    // prologue: 2 stages in flight
    load_stage(sb, 0, kbase + 0, tm, tn, tid);
    asm volatile("cp.async.commit_group;");
    load_stage(sb, 1, kbase + 1, tm, tn, tid);
    asm volatile("cp.async.commit_group;");

    // one k-tile body at compile-time stage index; t is local to the K half
    auto body = [&](int t, int sc) {
        asm volatile("cp.async.wait_group 1;");
        __syncthreads();

        if (t + 2 < NKT_H) {
            int sld = sc + 2; if (sld >= STAGES) sld -= STAGES;
            load_stage(sb, sld, kbase + t + 2, tm, tn, tid);
        }
        asm volatile("cp.async.commit_group;");   // empty group ok

        const uint32_t stg = sb + SM_TILES + (uint32_t)sc * STAGE_BYTES;
#pragma unroll
        for (int s = 0; s < 4; ++s) {             // four k16 steps per BK=64
            uint32_t a[4][4], b[4][4];
#pragma unroll
            for (int mt = 0; mt < 4; ++mt) {
                uint32_t ca = (uint32_t)(2 * s) + cAsel;
                ldsm4(a[mt], stg + OFF_A + aoff[mt] + ((ca ^ asw[mt]) << 4));
            }
#pragma unroll
            for (int jj = 0; jj < 4; ++jj) {
                uint32_t cb = (uint32_t)(2 * s) + cBsel;
                ldsm4(b[jj], stg + OFF_B + boff[jj] + ((cb ^ bsw[jj]) << 4));
            }
#pragma unroll
            for (int jj = 0; jj < 4; ++jj) {
                const int n0 = 2 * jj, n1 = 2 * jj + 1;
#pragma unroll
                for (int mt = 0; mt < 4; ++mt) {
                    mma16816(acc[mt][n0], a[mt], b[jj]);
                    mma16816(acc[mt][n1], a[mt], b[jj] + 2);
                }
            }
        }
    };

    // 32 k-tiles = 10 x (ring of 3, compile-time stages) + 2 tail
#pragma unroll 1
    for (int tt = 0; tt < NKT_H - 2; tt += 3) {
        body(tt, 0);
        body(tt + 1, 1);
        body(tt + 2, 2);
    }
    body(NKT_H - 2, 0);
    body(NKT_H - 1, 1);

    // epilogue: kh=0 adds bias; both halves red.add into out
    __syncthreads();
    const float* sbias = reinterpret_cast<const float*>(smem + SM_BIAS);
    const float bs = (kh == 0) ? 1.f : 0.f;
#pragma unroll
    for (int mt = 0; mt < 4; ++mt) {
#pragma unroll
        for (int nt = 0; nt < 8; ++nt) {
            int row = tm * BM + wm * 64 + mt * 16 + (lane >> 2);
            int cl = wn * 64 + nt * 8 + 2 * (lane & 3);
            float b0 = bs * sbias[cl], b1 = bs * sbias[cl + 1];
            float* p0 = out + (size_t)row * DIM + tn * BN + cl;
            float* p1 = p0 + 8 * DIM;
            redadd(p0,     acc[mt][nt][0] + b0);
            redadd(p0 + 1, acc[mt][nt][1] + b1);
            redadd(p1,     acc[mt][nt][2] + b0);
            redadd(p1 + 1, acc[mt][nt][3] + b1);
        }
    }
}

// ---------------------------------------------------------------------------
// Launch
// ---------------------------------------------------------------------------
extern "C" void kernel_launch(void* const* d_in, const int* in_sizes, int n_in,
                              void* d_out, int out_size) {
    const float* x = (const float*)d_in[0];
    const float* W = (const float*)d_in[1];
    const float* b = (const float*)d_in[2];
    float* out = (float*)d_out;

    // 3 segments x 8192 blocks: convert x, convert W, zero out
    convert_kernel<<<24576, 256>>>(x, W, out);

    cudaFuncSetAttribute(gemm_kernel, cudaFuncAttributeMaxDynamicSharedMemorySize,
                         SMEM_TOTAL);
    // 1024 tiles x 2 K-halves
    gemm_kernel<<<2048, THREADS, SMEM_TOTAL>>>(b, out);
}